// round 1
// baseline (speedup 1.0000x reference)
#include <cuda_runtime.h>
#include <cstdint>

#define N_USERS    50000
#define N_ENTITIES 150000
#define N_NODES    200000
#define N_EDGES    3200000
#define BATCH      4096

// ---------------- scratch (device globals; no allocation allowed) ----------
__device__ __align__(16) float g_hneigh[(size_t)N_NODES * 64];
__device__ __align__(16) float g_h1[(size_t)N_NODES * 64];
__device__ __align__(16) float g_h2[(size_t)N_NODES * 32];

__device__ __forceinline__ const float* feat0_row(const float* uw, const float* ew, int n) {
    return (n < N_USERS) ? (uw + (size_t)n * 64) : (ew + (size_t)(n - N_USERS) * 64);
}

// ---------------- zero h_neigh --------------------------------------------
__global__ void __launch_bounds__(256) k_zero_hneigh() {
    size_t i = (size_t)blockIdx.x * 256 + threadIdx.x;   // grid covers exactly N_NODES*64/4
    ((float4*)g_hneigh)[i] = make_float4(0.f, 0.f, 0.f, 0.f);
}

// ---------------- edge aggregation: h_neigh[t] += feat[nb] * v -------------
// 16 threads per edge, one float4 + red.global.add.v4.f32 each.
template <int LAYER>
__global__ void __launch_bounds__(256) k_agg(const float* __restrict__ uw,
                                             const float* __restrict__ ew,
                                             const int*   __restrict__ target,
                                             const int*   __restrict__ neighbor,
                                             const float* __restrict__ values) {
    unsigned idx = blockIdx.x * 256u + threadIdx.x;
    unsigned e = idx >> 4;
    int c = idx & 15;
    if (e >= N_EDGES) return;
    int nb = neighbor[e];
    int t  = target[e];
    float v = values[e];
    const float* src = (LAYER == 1) ? feat0_row(uw, ew, nb) : (g_h1 + (size_t)nb * 64);
    float4 f = *(const float4*)(src + c * 4);
    float* dst = g_hneigh + (size_t)t * 64 + c * 4;
    asm volatile("red.global.add.v4.f32 [%0], {%1, %2, %3, %4};"
                 :: "l"(dst), "f"(f.x * v), "f"(f.y * v), "f"(f.z * v), "f"(f.w * v)
                 : "memory");
}

// ---------------- dense layer 1: 64 -> 64, leaky relu, l2 norm -------------
// blockDim = (64, 4): 4 nodes per block, 64 threads (= output cols) per node.
__global__ void __launch_bounds__(256) k_dense1(const float* __restrict__ uw,
                                                const float* __restrict__ ew,
                                                const float* __restrict__ W1,
                                                const float* __restrict__ b1,
                                                const float* __restrict__ W2,
                                                const float* __restrict__ b2) {
    __shared__ float W1s[64 * 64];
    __shared__ float W2s[64 * 64];
    __shared__ float sArr[4][64];   // f + g
    __shared__ float pArr[4][64];   // f * g
    __shared__ float red2[4][2];

    int ty = threadIdx.y;
    int j  = threadIdx.x;
    int tid = ty * 64 + j;
    for (int i = tid; i < 64 * 64; i += 256) { W1s[i] = W1[i]; W2s[i] = W2[i]; }

    int n = blockIdx.x * 4 + ty;    // grid = 50000 blocks, exact
    const float* f = feat0_row(uw, ew, n);
    float fj = f[j];
    float gj = g_hneigh[(size_t)n * 64 + j];
    __syncthreads();                // W1s/W2s ready
    sArr[ty][j] = fj + gj;
    pArr[ty][j] = fj * gj;
    __syncthreads();

    float acc = b1[j] + b2[j];
    #pragma unroll
    for (int k = 0; k < 64; k++) {
        acc = fmaf(sArr[ty][k], W1s[k * 64 + j], acc);
        acc = fmaf(pArr[ty][k], W2s[k * 64 + j], acc);
    }
    acc = (acc >= 0.f) ? acc : 0.01f * acc;   // leaky relu

    // l2 norm over 64 cols (2 warps per node)
    float sq = acc * acc;
    #pragma unroll
    for (int o = 16; o > 0; o >>= 1) sq += __shfl_xor_sync(0xffffffffu, sq, o);
    if ((j & 31) == 0) red2[ty][j >> 5] = sq;
    __syncthreads();
    float tot = red2[ty][0] + red2[ty][1];
    float inv = 1.f / fmaxf(sqrtf(tot), 1e-12f);
    g_h1[(size_t)n * 64 + j] = acc * inv;
}

// ---------------- dense layer 2: 64 -> 32, leaky relu, l2 norm -------------
// blockDim = (32, 8): one warp per node.
__global__ void __launch_bounds__(256) k_dense2(const float* __restrict__ W1,
                                                const float* __restrict__ b1,
                                                const float* __restrict__ W2,
                                                const float* __restrict__ b2) {
    __shared__ float W1s[64 * 32];
    __shared__ float W2s[64 * 32];
    __shared__ float sArr[8][64];
    __shared__ float pArr[8][64];

    int ty = threadIdx.y;
    int j  = threadIdx.x;
    int tid = ty * 32 + j;
    for (int i = tid; i < 64 * 32; i += 256) { W1s[i] = W1[i]; W2s[i] = W2[i]; }

    int n = blockIdx.x * 8 + ty;    // grid = 25000 blocks, exact
    #pragma unroll
    for (int r = 0; r < 2; r++) {
        int k = j + r * 32;
        float fk = g_h1[(size_t)n * 64 + k];
        float gk = g_hneigh[(size_t)n * 64 + k];
        sArr[ty][k] = fk + gk;
        pArr[ty][k] = fk * gk;
    }
    __syncthreads();                // covers weight load too

    float acc = b1[j] + b2[j];
    #pragma unroll
    for (int k = 0; k < 64; k++) {
        acc = fmaf(sArr[ty][k], W1s[k * 32 + j], acc);
        acc = fmaf(pArr[ty][k], W2s[k * 32 + j], acc);
    }
    acc = (acc >= 0.f) ? acc : 0.01f * acc;

    float sq = acc * acc;
    #pragma unroll
    for (int o = 16; o > 0; o >>= 1) sq += __shfl_xor_sync(0xffffffffu, sq, o);
    float inv = 1.f / fmaxf(sqrtf(sq), 1e-12f);
    g_h2[(size_t)n * 32 + j] = acc * inv;
}

// ---------------- scoring: one warp per batch element ----------------------
__global__ void __launch_bounds__(256) k_score(const float* __restrict__ uw,
                                               const float* __restrict__ ew,
                                               const int* __restrict__ uid,
                                               const int* __restrict__ pid,
                                               const int* __restrict__ nid,
                                               float* __restrict__ out) {
    int gidx = blockIdx.x * 256 + threadIdx.x;
    int b = gidx >> 5;
    int l = gidx & 31;
    if (b >= BATCH) return;
    int u  = uid[b];                 // user node id (< N_USERS)
    int pe = pid[b];                 // entity-local indices
    int ne = nid[b];
    int p  = N_USERS + pe;
    int q  = N_USERS + ne;

    const float* fu = uw + (size_t)u * 64;
    const float* fp = ew + (size_t)pe * 64;
    const float* fq = ew + (size_t)ne * 64;

    float sp = 0.f, sn = 0.f;
    // dims 0..63 : ego embedding
    #pragma unroll
    for (int r = 0; r < 2; r++) {
        int c = l + r * 32;
        float a = fu[c];
        sp = fmaf(a, fp[c], sp);
        sn = fmaf(a, fq[c], sn);
    }
    // dims 64..127 : h1
    #pragma unroll
    for (int r = 0; r < 2; r++) {
        int c = l + r * 32;
        float a = g_h1[(size_t)u * 64 + c];
        sp = fmaf(a, g_h1[(size_t)p * 64 + c], sp);
        sn = fmaf(a, g_h1[(size_t)q * 64 + c], sn);
    }
    // dims 128..159 : h2
    {
        float a = g_h2[(size_t)u * 32 + l];
        sp = fmaf(a, g_h2[(size_t)p * 32 + l], sp);
        sn = fmaf(a, g_h2[(size_t)q * 32 + l], sn);
    }
    #pragma unroll
    for (int o = 16; o > 0; o >>= 1) {
        sp += __shfl_xor_sync(0xffffffffu, sp, o);
        sn += __shfl_xor_sync(0xffffffffu, sn, o);
    }
    if (l == 0) { out[b] = sp; out[BATCH + b] = sn; }
}

// ---------------- launch ---------------------------------------------------
extern "C" void kernel_launch(void* const* d_in, const int* in_sizes, int n_in,
                              void* d_out, int out_size) {
    const float* uw   = (const float*)d_in[0];
    const float* ew   = (const float*)d_in[1];
    const float* W1a  = (const float*)d_in[2];
    const float* b1a  = (const float*)d_in[3];
    const float* W2a  = (const float*)d_in[4];
    const float* b2a  = (const float*)d_in[5];
    const float* W1b  = (const float*)d_in[6];
    const float* b1b  = (const float*)d_in[7];
    const float* W2b  = (const float*)d_in[8];
    const float* b2b  = (const float*)d_in[9];
    const float* values   = (const float*)d_in[10];
    const int*   target   = (const int*)d_in[11];
    const int*   neighbor = (const int*)d_in[12];
    const int*   uid      = (const int*)d_in[13];
    const int*   pid      = (const int*)d_in[14];
    const int*   nid      = (const int*)d_in[15];
    float* out = (float*)d_out;

    const int zeroBlocks = (N_NODES * 64 / 4) / 256;          // 12500, exact
    const int aggBlocks  = (N_EDGES * 16) / 256;              // 200000, exact

    // Layer 1
    k_zero_hneigh<<<zeroBlocks, 256>>>();
    k_agg<1><<<aggBlocks, 256>>>(uw, ew, target, neighbor, values);
    k_dense1<<<N_NODES / 4, dim3(64, 4)>>>(uw, ew, W1a, b1a, W2a, b2a);

    // Layer 2
    k_zero_hneigh<<<zeroBlocks, 256>>>();
    k_agg<2><<<aggBlocks, 256>>>(uw, ew, target, neighbor, values);
    k_dense2<<<N_NODES / 8, dim3(32, 8)>>>(W1b, b1b, W2b, b2b);

    // Scores
    k_score<<<(BATCH * 32) / 256, 256>>>(uw, ew, uid, pid, nid, out);
}

// round 2
// speedup vs baseline: 1.9789x; 1.9789x over previous
#include <cuda_runtime.h>
#include <cstdint>

#define N_USERS    50000
#define N_ENTITIES 150000
#define N_NODES    200000
#define N_EDGES    3200000
#define BATCH      4096

typedef unsigned long long ull;

// ---------------- scratch (device globals; no allocation allowed) ----------
__device__ __align__(16) float g_hneigh[(size_t)N_NODES * 64];
__device__ __align__(16) float g_h1[(size_t)N_NODES * 64];
__device__ __align__(16) float g_h2[(size_t)N_NODES * 32];
__device__ __align__(16) int   g_count[N_NODES];
__device__ __align__(16) int   g_rowstart[N_NODES + 1];
__device__ __align__(16) int   g_cursor[N_NODES];
__device__ __align__(16) int2  g_srt[N_EDGES];      // {neighbor, value-bits} sorted by target

__device__ __forceinline__ const float* feat0_row(const float* uw, const float* ew, int n) {
    return (n < N_USERS) ? (uw + (size_t)n * 64) : (ew + (size_t)(n - N_USERS) * 64);
}

__device__ __forceinline__ void ffma2(ull& d, ull a, ull b) {
    asm("fma.rn.f32x2 %0, %1, %2, %0;" : "+l"(d) : "l"(a), "l"(b));
}

// ---------------- CSR build ------------------------------------------------
__global__ void __launch_bounds__(256) k_zero_counts() {
    int i = blockIdx.x * 256 + threadIdx.x;           // int4 index
    if (i < N_NODES / 4) ((int4*)g_count)[i] = make_int4(0, 0, 0, 0);
}

__global__ void __launch_bounds__(256) k_count(const int* __restrict__ target) {
    int e = blockIdx.x * 256 + threadIdx.x;           // grid exact: 3.2M/256
    atomicAdd(&g_count[target[e]], 1);                // RED.ADD, no return
}

__global__ void __launch_bounds__(1024) k_scan() {
    const int CH = (N_NODES + 1023) / 1024;           // 196
    __shared__ int sa[1024], sb[1024];
    int t = threadIdx.x;
    int beg = t * CH;
    int end = beg + CH; if (end > N_NODES) end = N_NODES;
    int sum = 0;
    for (int i = beg; i < end; i++) sum += g_count[i];
    sa[t] = sum;
    __syncthreads();
    int* src = sa; int* dst = sb;
    for (int off = 1; off < 1024; off <<= 1) {
        dst[t] = (t >= off) ? src[t] + src[t - off] : src[t];
        __syncthreads();
        int* tmp = src; src = dst; dst = tmp;
    }
    int run = (t > 0) ? src[t - 1] : 0;               // exclusive prefix
    for (int i = beg; i < end; i++) {
        g_rowstart[i] = run;
        g_cursor[i]   = run;
        run += g_count[i];
    }
    if (t == 0) g_rowstart[N_NODES] = N_EDGES;
}

__global__ void __launch_bounds__(256) k_scatter(const int* __restrict__ target,
                                                const int* __restrict__ neighbor,
                                                const float* __restrict__ values) {
    int e = blockIdx.x * 256 + threadIdx.x;           // grid exact
    int t = target[e];
    int pos = atomicAdd(&g_cursor[t], 1);
    g_srt[pos] = make_int2(neighbor[e], __float_as_int(values[e]));
}

// ---------------- CSR gather: h_neigh[n] = sum_e feat[nb_e]*v_e -----------
// One warp per node: 16 lanes = float4 chunks, 2 edges in flight.
template <int LAYER>
__global__ void __launch_bounds__(256) k_gather(const float* __restrict__ uw,
                                                const float* __restrict__ ew) {
    int n = (blockIdx.x * 256 + threadIdx.x) >> 5;    // grid exact: 25000*8 warps
    int lane = threadIdx.x & 31;
    int c = lane & 15, half = lane >> 4;
    int base = g_rowstart[n];
    int end  = g_rowstart[n + 1];
    float4 acc = make_float4(0.f, 0.f, 0.f, 0.f);
    for (int i = base + half; i < end; i += 2) {
        int2 e = g_srt[i];
        float v = __int_as_float(e.y);
        const float* src = (LAYER == 1) ? feat0_row(uw, ew, e.x)
                                        : (g_h1 + (size_t)e.x * 64);
        float4 f = *(const float4*)(src + c * 4);
        acc.x = fmaf(f.x, v, acc.x);
        acc.y = fmaf(f.y, v, acc.y);
        acc.z = fmaf(f.z, v, acc.z);
        acc.w = fmaf(f.w, v, acc.w);
    }
    acc.x += __shfl_xor_sync(0xffffffffu, acc.x, 16);
    acc.y += __shfl_xor_sync(0xffffffffu, acc.y, 16);
    acc.z += __shfl_xor_sync(0xffffffffu, acc.z, 16);
    acc.w += __shfl_xor_sync(0xffffffffu, acc.w, 16);
    if (half == 0)
        *(float4*)(g_hneigh + (size_t)n * 64 + c * 4) = acc;
}

// ---------------- dense layer as register-tiled GEMM -----------------------
// out = leakyrelu( [s|p] @ [W1;W2] + b1 + b2 ), then row-l2norm.
// K = 128 (s: k 0..63, p: k 64..127), processed in 4 chunks of 32.
// LAYER=1: NOUT=64, TM=64.  LAYER=2: NOUT=32, TM=128.
// Thread (r,c): 4 nodes (r*4..+3) x 4 cols (c + jj*CQ), fma.rn.f32x2 over k-pairs.
template <int LAYER>
__global__ void __launch_bounds__(256) k_dense(const float* __restrict__ uw,
                                               const float* __restrict__ ew,
                                               const float* __restrict__ W1,
                                               const float* __restrict__ b1,
                                               const float* __restrict__ W2,
                                               const float* __restrict__ b2) {
    constexpr int NOUT = (LAYER == 1) ? 64 : 32;
    constexpr int CQ   = NOUT / 4;          // 16 / 8
    constexpr int TM   = (256 / CQ) * 4;    // 64 / 128

    __shared__ __align__(16) float2 As2[TM][16];     // [node][k-pair] per chunk
    __shared__ __align__(16) float2 Bs2[16][NOUT];   // [k-pair][col]

    int tid = threadIdx.x;
    int r = tid / CQ;       // node quad
    int c = tid % CQ;       // col within group
    int blockBase = blockIdx.x * TM;

    // bias per thread column
    float bsum[4];
    #pragma unroll
    for (int jj = 0; jj < 4; jj++) {
        int j = c + jj * CQ;
        bsum[jj] = b1[j] + b2[j];
    }

    ull acc[4][4];
    #pragma unroll
    for (int i = 0; i < 4; i++)
        #pragma unroll
        for (int jj = 0; jj < 4; jj++) acc[i][jj] = 0ull;

    for (int kk = 0; kk < 4; kk++) {
        // ---- load A chunk: s or p, cols base_col..base_col+31 ----
        int base_col = (kk & 1) * 32;
        bool isP = (kk >= 2);
        for (int idx = tid; idx < TM * 8; idx += 256) {     // float4 granularity
            int m  = idx >> 3;
            int q4 = idx & 7;
            int node = blockBase + m;
            float4 fv = make_float4(0.f, 0.f, 0.f, 0.f);
            float4 gv = fv;
            if (node < N_NODES) {
                const float* fr = (LAYER == 1) ? feat0_row(uw, ew, node)
                                               : (g_h1 + (size_t)node * 64);
                fv = *(const float4*)(fr + base_col + q4 * 4);
                gv = *(const float4*)(g_hneigh + (size_t)node * 64 + base_col + q4 * 4);
            }
            float4 a;
            if (isP) { a.x = fv.x * gv.x; a.y = fv.y * gv.y; a.z = fv.z * gv.z; a.w = fv.w * gv.w; }
            else     { a.x = fv.x + gv.x; a.y = fv.y + gv.y; a.z = fv.z + gv.z; a.w = fv.w + gv.w; }
            As2[m][q4 * 2]     = make_float2(a.x, a.y);
            As2[m][q4 * 2 + 1] = make_float2(a.z, a.w);
        }
        // ---- load B chunk (k-pairs transposed into float2) ----
        for (int idx = tid; idx < 16 * NOUT; idx += 256) {
            int kp = idx / NOUT;
            int j  = idx % NOUT;
            int kg = kk * 32 + kp * 2;     // 0..126, same matrix for kg and kg+1
            float w0, w1;
            if (kg < 64) { w0 = W1[kg * NOUT + j];        w1 = W1[(kg + 1) * NOUT + j]; }
            else         { w0 = W2[(kg - 64) * NOUT + j]; w1 = W2[(kg - 63) * NOUT + j]; }
            Bs2[kp][j] = make_float2(w0, w1);
        }
        __syncthreads();

        // ---- mainloop: 16 k-pairs ----
        #pragma unroll
        for (int kp = 0; kp < 16; kp++) {
            ull a[4], b[4];
            #pragma unroll
            for (int i = 0; i < 4; i++)  a[i]  = *(const ull*)&As2[r * 4 + i][kp];
            #pragma unroll
            for (int jj = 0; jj < 4; jj++) b[jj] = *(const ull*)&Bs2[kp][c + jj * CQ];
            #pragma unroll
            for (int i = 0; i < 4; i++)
                #pragma unroll
                for (int jj = 0; jj < 4; jj++)
                    ffma2(acc[i][jj], a[i], b[jj]);
        }
        __syncthreads();
    }

    // ---- epilogue: bias, leaky relu, row l2-norm, store ----
    float* OUT = (LAYER == 1) ? g_h1 : g_h2;
    #pragma unroll
    for (int i = 0; i < 4; i++) {
        int node = blockBase + r * 4 + i;
        float v[4];
        float sq = 0.f;
        #pragma unroll
        for (int jj = 0; jj < 4; jj++) {
            ull x = acc[i][jj];
            float lo = __uint_as_float((unsigned)(x & 0xffffffffull));
            float hi = __uint_as_float((unsigned)(x >> 32));
            float s = lo + hi + bsum[jj];
            s = (s >= 0.f) ? s : 0.01f * s;
            v[jj] = s;
            sq = fmaf(s, s, sq);
        }
        #pragma unroll
        for (int off = CQ / 2; off > 0; off >>= 1)
            sq += __shfl_xor_sync(0xffffffffu, sq, off);
        float inv = 1.f / fmaxf(sqrtf(sq), 1e-12f);
        if (node < N_NODES) {
            #pragma unroll
            for (int jj = 0; jj < 4; jj++)
                OUT[(size_t)node * NOUT + c + jj * CQ] = v[jj] * inv;
        }
    }
}

// ---------------- scoring: one warp per batch element ----------------------
__global__ void __launch_bounds__(256) k_score(const float* __restrict__ uw,
                                               const float* __restrict__ ew,
                                               const int* __restrict__ uid,
                                               const int* __restrict__ pid,
                                               const int* __restrict__ nid,
                                               float* __restrict__ out) {
    int gidx = blockIdx.x * 256 + threadIdx.x;
    int b = gidx >> 5;
    int l = gidx & 31;
    if (b >= BATCH) return;
    int u  = uid[b];
    int pe = pid[b];
    int ne = nid[b];
    int p  = N_USERS + pe;
    int q  = N_USERS + ne;

    const float* fu = uw + (size_t)u * 64;
    const float* fp = ew + (size_t)pe * 64;
    const float* fq = ew + (size_t)ne * 64;

    float sp = 0.f, sn = 0.f;
    #pragma unroll
    for (int r = 0; r < 2; r++) {
        int cidx = l + r * 32;
        float a = fu[cidx];
        sp = fmaf(a, fp[cidx], sp);
        sn = fmaf(a, fq[cidx], sn);
    }
    #pragma unroll
    for (int r = 0; r < 2; r++) {
        int cidx = l + r * 32;
        float a = g_h1[(size_t)u * 64 + cidx];
        sp = fmaf(a, g_h1[(size_t)p * 64 + cidx], sp);
        sn = fmaf(a, g_h1[(size_t)q * 64 + cidx], sn);
    }
    {
        float a = g_h2[(size_t)u * 32 + l];
        sp = fmaf(a, g_h2[(size_t)p * 32 + l], sp);
        sn = fmaf(a, g_h2[(size_t)q * 32 + l], sn);
    }
    #pragma unroll
    for (int o = 16; o > 0; o >>= 1) {
        sp += __shfl_xor_sync(0xffffffffu, sp, o);
        sn += __shfl_xor_sync(0xffffffffu, sn, o);
    }
    if (l == 0) { out[b] = sp; out[BATCH + b] = sn; }
}

// ---------------- launch ---------------------------------------------------
extern "C" void kernel_launch(void* const* d_in, const int* in_sizes, int n_in,
                              void* d_out, int out_size) {
    const float* uw   = (const float*)d_in[0];
    const float* ew   = (const float*)d_in[1];
    const float* W1a  = (const float*)d_in[2];
    const float* b1a  = (const float*)d_in[3];
    const float* W2a  = (const float*)d_in[4];
    const float* b2a  = (const float*)d_in[5];
    const float* W1b  = (const float*)d_in[6];
    const float* b1b  = (const float*)d_in[7];
    const float* W2b  = (const float*)d_in[8];
    const float* b2b  = (const float*)d_in[9];
    const float* values   = (const float*)d_in[10];
    const int*   target   = (const int*)d_in[11];
    const int*   neighbor = (const int*)d_in[12];
    const int*   uid      = (const int*)d_in[13];
    const int*   pid      = (const int*)d_in[14];
    const int*   nid      = (const int*)d_in[15];
    float* out = (float*)d_out;

    // CSR build (once; reused by both layers)
    k_zero_counts<<<(N_NODES / 4 + 255) / 256, 256>>>();
    k_count<<<N_EDGES / 256, 256>>>(target);
    k_scan<<<1, 1024>>>();
    k_scatter<<<N_EDGES / 256, 256>>>(target, neighbor, values);

    // Layer 1
    k_gather<1><<<N_NODES / 8, 256>>>(uw, ew);
    k_dense<1><<<N_NODES / 64, 256>>>(uw, ew, W1a, b1a, W2a, b2a);

    // Layer 2
    k_gather<2><<<N_NODES / 8, 256>>>(uw, ew);
    k_dense<2><<<(N_NODES + 127) / 128, 256>>>(uw, ew, W1b, b1b, W2b, b2b);

    // Scores
    k_score<<<(BATCH * 32) / 256, 256>>>(uw, ew, uid, pid, nid, out);
}